// round 4
// baseline (speedup 1.0000x reference)
#include <cuda_runtime.h>
#include <cuda_fp16.h>
#include <cstdint>

#define H 512
#define W 512
#define NPIX (H * W)

// Packed flow-corner table: entry (i,j) = 16 bytes =
//   half2 f(i,j), half2 f(i,j+1), half2 f(i+1,j), half2 f(i+1,j+1)
// where f = (flow_ch0, flow_ch1). One LDG.128 per bilinear sample.
__device__ uint4 g_F[NPIX];   // 4 MB, L2-resident

__device__ __forceinline__ uint32_t pack_h2(float a, float b) {
    __half2 h = __floats2half2_rn(a, b);
    return *reinterpret_cast<uint32_t*>(&h);
}

__global__ void build_F_kernel(const float* __restrict__ flow) {
    int idx = blockIdx.x * blockDim.x + threadIdx.x;
    if (idx >= NPIX) return;
    int i = idx >> 9;
    int j = idx & (W - 1);
    int i1 = min(i + 1, H - 1);
    int j1 = min(j + 1, W - 1);
    int p00 = (i  << 9) | j;
    int p01 = (i  << 9) | j1;
    int p10 = (i1 << 9) | j;
    int p11 = (i1 << 9) | j1;
    uint4 e;
    e.x = pack_h2(flow[p00], flow[NPIX + p00]);
    e.y = pack_h2(flow[p01], flow[NPIX + p01]);
    e.z = pack_h2(flow[p10], flow[NPIX + p10]);
    e.w = pack_h2(flow[p11], flow[NPIX + p11]);
    g_F[idx] = e;
}

__device__ __forceinline__ float2 unpack_h2(uint32_t u) {
    __half2 h = *reinterpret_cast<__half2*>(&u);
    return __half22float2(h);
}

#define OUT_SCALE (512.0f / 511.0f)

// Phase 1: compute table key + fractional parts for one point.
struct PointCtx {
    int   key;
    float xf, yf;
    int   x0, y0;
};

__device__ __forceinline__ PointCtx point_setup(float x, float y, bool bilinear) {
    PointCtx c;
    if (bilinear) {
        float xt = truncf(x);
        float yt = truncf(y);
        c.xf = x - xt;
        c.yf = y - yt;
        c.x0 = (int)xt;
        c.y0 = (int)yt;
        c.key = (c.x0 << 9) | c.y0;
    } else {
        c.x0 = min((int)rintf(x), H - 1);
        c.y0 = min((int)rintf(y), W - 1);
        c.xf = 0.0f; c.yf = 0.0f;
        c.key = (c.x0 << 9) | c.y0;
    }
    return c;
}

// Phase 2: combine gathered entry with fractional weights.
__device__ __forceinline__ float2 point_finish(const PointCtx& c, uint4 e, bool bilinear) {
    if (bilinear) {
        float2 c00 = unpack_h2(e.x);
        float2 c01 = unpack_h2(e.y);
        float2 c10 = unpack_h2(e.z);
        float2 c11 = unpack_h2(e.w);
        float oxf = 1.0f - c.xf;
        float oyf = 1.0f - c.yf;
        float w00 = c.xf * c.yf;
        float w10 = c.xf * oyf;
        float w01 = oxf * c.yf;
        float w11 = oxf * oyf;
        float bf0 = fmaf(w00, c00.x, fmaf(w10, c10.x, fmaf(w01, c01.x, w11 * c11.x)));
        float bf1 = fmaf(w00, c00.y, fmaf(w10, c10.y, fmaf(w01, c01.y, w11 * c11.y)));
        float out0 = ((float)(c.x0 + 1) - c.yf + bf0) * OUT_SCALE;
        float out1 = ((float)(c.y0 + 1) - c.xf + bf1) * OUT_SCALE;
        return make_float2(out0, out1);
    } else {
        float2 c00 = unpack_h2(e.x);
        return make_float2(((float)c.x0 + c00.x) * OUT_SCALE,
                           ((float)c.y0 + c00.y) * OUT_SCALE);
    }
}

// 4 points per thread: batch the 4 independent gathers for MLP.
__global__ void sample_kernel(const float4* __restrict__ pts,
                              float4* __restrict__ out,
                              const int* __restrict__ intep,
                              int n_quad) {
    int idx = blockIdx.x * blockDim.x + threadIdx.x;
    if (idx >= n_quad) return;
    bool bilinear = (*intep) != 0;

    // Load 4 points (2 x float4), streaming (evict-first) to protect table in L2.
    float4 pa = __ldcs(pts + 2 * idx);
    float4 pb = __ldcs(pts + 2 * idx + 1);

    PointCtx c0 = point_setup(pa.x, pa.y, bilinear);
    PointCtx c1 = point_setup(pa.z, pa.w, bilinear);
    PointCtx c2 = point_setup(pb.x, pb.y, bilinear);
    PointCtx c3 = point_setup(pb.z, pb.w, bilinear);

    // 4 independent gathers in flight.
    uint4 e0 = __ldg(g_F + c0.key);
    uint4 e1 = __ldg(g_F + c1.key);
    uint4 e2 = __ldg(g_F + c2.key);
    uint4 e3 = __ldg(g_F + c3.key);

    float2 r0 = point_finish(c0, e0, bilinear);
    float2 r1 = point_finish(c1, e1, bilinear);
    float2 r2 = point_finish(c2, e2, bilinear);
    float2 r3 = point_finish(c3, e3, bilinear);

    __stcs(out + 2 * idx,     make_float4(r0.x, r0.y, r1.x, r1.y));
    __stcs(out + 2 * idx + 1, make_float4(r2.x, r2.y, r3.x, r3.y));
}

extern "C" void kernel_launch(void* const* d_in, const int* in_sizes, int n_in,
                              void* d_out, int out_size) {
    const float* point = (const float*)d_in[0];   // (1, N, 2)
    const float* flow  = (const float*)d_in[1];   // (1, 2, 512, 512)
    const int*   intep = (const int*)d_in[2];

    build_F_kernel<<<(NPIX + 255) / 256, 256>>>(flow);

    int n_quad = out_size / 8;  // 4 points (8 floats) per thread
    sample_kernel<<<(n_quad + 255) / 256, 256>>>(
        (const float4*)point, (float4*)d_out, intep, n_quad);
}